// round 1
// baseline (speedup 1.0000x reference)
#include <cuda_runtime.h>

#define BQ 16      // batch
#define NH 32      // heads
#define HD 128     // head dim
#define LL 4096    // seq len
#define CC 1536    // q_lora_rank
#define NW 8       // warps per attention CTA

// Scratch for projected q: [B, H, HD] = 16*32*128 floats = 256 KB.
__device__ float g_q[BQ * NH * HD];

// ---------------------------------------------------------------------------
// Kernel 1: q = hidden @ w_q^T + b_q
// grid = 512 blocks, blockIdx.x = h*16 + b (batches sharing w_q rows adjacent
// for L2 reuse), 128 threads, thread k computes q[b,h,k] as a 1536-dot.
// ---------------------------------------------------------------------------
__global__ void __launch_bounds__(HD) qproj_kernel(const float* __restrict__ hidden,
                                                   const float* __restrict__ wq,
                                                   const float* __restrict__ bq) {
    const int h = blockIdx.x >> 4;
    const int b = blockIdx.x & 15;
    const int k = threadIdx.x;

    __shared__ float sh[CC];
    #pragma unroll
    for (int i = k; i < CC; i += HD) sh[i] = hidden[b * CC + i];
    __syncthreads();

    const int row = h * HD + k;
    const float4* wp = reinterpret_cast<const float4*>(wq + (size_t)row * CC);
    float acc = 0.0f;
    #pragma unroll 8
    for (int c4 = 0; c4 < CC / 4; c4++) {
        float4 wv = wp[c4];
        float4 hv = *reinterpret_cast<const float4*>(sh + 4 * c4);
        acc += wv.x * hv.x + wv.y * hv.y + wv.z * hv.z + wv.w * hv.w;
    }
    g_q[(b * NH + h) * HD + k] = acc + bq[row];
}

// ---------------------------------------------------------------------------
// Kernel 2: fused scores -> softmax -> weighted V, single pass over L.
// grid = B*H = 512 CTAs, 256 threads (8 warps). Warp w streams l in
// [w*512, (w+1)*512). Lane holds k = 4*lane..4*lane+3 slice of q/acc.
// Online softmax with warp-uniform rescale branch.
// ---------------------------------------------------------------------------
__global__ void __launch_bounds__(NW * 32) attn_kernel(const float* __restrict__ Kd,
                                                       const float* __restrict__ Vd,
                                                       float* __restrict__ out) {
    const int bh   = blockIdx.x;          // b*NH + h
    const int b    = bh >> 5;
    const int h    = bh & 31;
    const int warp = threadIdx.x >> 5;
    const int lane = threadIdx.x & 31;

    const float4 qv = *reinterpret_cast<const float4*>(g_q + (size_t)bh * HD + 4 * lane);

    const int S4  = NH * HD / 4;          // float4 stride between l's = 1024
    const int LPW = LL / NW;              // 512 l per warp
    const size_t base4 = (((size_t)b * LL) * NH + h) * (HD / 4);

    const float4* kp = reinterpret_cast<const float4*>(Kd) + base4
                       + (size_t)(warp * LPW) * S4 + lane;
    const float4* vp = reinterpret_cast<const float4*>(Vd) + base4
                       + (size_t)(warp * LPW) * S4 + lane;

    float m = -1e30f;                     // running max
    float s = 0.0f;                       // running denom
    float ax = 0.f, ay = 0.f, az = 0.f, aw = 0.f;   // running numerator (k slice)

    #pragma unroll 1
    for (int i = 0; i < LPW; i += 4) {
        // Batch the loads up front for MLP (8 outstanding LDG.128 per warp).
        float4 kv[4], vv[4];
        #pragma unroll
        for (int u = 0; u < 4; u++) {
            kv[u] = kp[u * S4];
            vv[u] = vp[u * S4];
        }
        kp += 4 * S4;
        vp += 4 * S4;

        #pragma unroll
        for (int u = 0; u < 4; u++) {
            float x = kv[u].x * qv.x + kv[u].y * qv.y + kv[u].z * qv.z + kv[u].w * qv.w;
            x += __shfl_xor_sync(0xffffffffu, x, 16);
            x += __shfl_xor_sync(0xffffffffu, x, 8);
            x += __shfl_xor_sync(0xffffffffu, x, 4);
            x += __shfl_xor_sync(0xffffffffu, x, 2);
            x += __shfl_xor_sync(0xffffffffu, x, 1);

            if (x > m) {                  // warp-uniform, rare (~ln(L) times)
                float sc = __expf(m - x);
                s *= sc; ax *= sc; ay *= sc; az *= sc; aw *= sc;
                m = x;
            }
            float p = __expf(x - m);
            s  += p;
            ax += p * vv[u].x;
            ay += p * vv[u].y;
            az += p * vv[u].z;
            aw += p * vv[u].w;
        }
    }

    // Cross-warp merge.
    __shared__ float  sm_m[NW];
    __shared__ float  sm_s[NW];
    __shared__ float4 sm_acc[NW][32];     // [warp][lane] -> k = 4*lane..+3

    if (lane == 0) { sm_m[warp] = m; sm_s[warp] = s; }
    sm_acc[warp][lane] = make_float4(ax, ay, az, aw);
    __syncthreads();

    if (threadIdx.x < HD) {
        const int k = threadIdx.x;
        float M = sm_m[0];
        #pragma unroll
        for (int w = 1; w < NW; w++) M = fmaxf(M, sm_m[w]);
        float denom = 0.0f, num = 0.0f;
        #pragma unroll
        for (int w = 0; w < NW; w++) {
            float e = __expf(sm_m[w] - M);
            denom += e * sm_s[w];
            num   += e * reinterpret_cast<const float*>(&sm_acc[w][0])[k];
        }
        out[(size_t)bh * HD + k] = num / denom;
    }
}

// ---------------------------------------------------------------------------
// Inputs (metadata order): 0 hidden_states_q [B,1536] f32
//                          1 key_states      [B,L,H,HD] f32
//                          2 value_states    [B,L,H,HD] f32
//                          3 w_q             [H*HD,1536] f32
//                          4 b_q             [H*HD] f32
// Output: [B, H*HD] f32
// ---------------------------------------------------------------------------
extern "C" void kernel_launch(void* const* d_in, const int* in_sizes, int n_in,
                              void* d_out, int out_size) {
    (void)in_sizes; (void)n_in; (void)out_size;
    const float* hidden = (const float*)d_in[0];
    const float* Kd     = (const float*)d_in[1];
    const float* Vd     = (const float*)d_in[2];
    const float* wq     = (const float*)d_in[3];
    const float* bq     = (const float*)d_in[4];
    float* out          = (float*)d_out;

    qproj_kernel<<<BQ * NH, HD>>>(hidden, wq, bq);
    attn_kernel<<<BQ * NH, NW * 32>>>(Kd, Vd, out);
}

// round 2
// speedup vs baseline: 1.1299x; 1.1299x over previous
#include <cuda_runtime.h>

#define BQ 16      // batch
#define NH 32      // heads
#define HD 128     // head dim
#define LL 4096    // seq len
#define CC 1536    // q_lora_rank
#define NW 8       // warps per attention CTA
#define SPLIT 4    // L-splits per (b,h)

// Scratch for projected q: [B, H, HD] = 256 KB.
__device__ float g_q[BQ * NH * HD];
// Partial softmax results: indexed by bhs = (b*NH+h)*SPLIT + s.
__device__ float g_pm[BQ * NH * SPLIT];
__device__ float g_ps[BQ * NH * SPLIT];
__device__ float g_pa[BQ * NH * SPLIT * HD];

// ---------------------------------------------------------------------------
// Kernel 1: q = hidden @ w_q^T + b_q      (16 x 1536 x 4096 GEMM)
// grid = 256 blocks; each block computes 16 w rows x all 16 batches.
// thread = (row_in_block, batch): tid = r*16 + b.
// w row loads are 16-lane broadcast; hidden staged transposed in smem
// (float4, stride 17 padding -> conflict-free LDS.128). w_q read from DRAM
// exactly once (25 MB).
// ---------------------------------------------------------------------------
#define C4 (CC / 4)         // 384 float4 per row
#define SHSTRIDE 17         // padded float4 stride over batch dim

__global__ void __launch_bounds__(256) qproj_kernel(const float* __restrict__ hidden,
                                                    const float* __restrict__ wq,
                                                    const float* __restrict__ bq) {
    extern __shared__ float4 sh4[];       // [C4][SHSTRIDE] -> sh4[c4*17 + b]
    const int tid = threadIdx.x;
    const int b   = tid & 15;
    const int r   = tid >> 4;             // 0..15

    // Stage hidden[16][1536] transposed: sh4[c4*17 + b] = hidden4[b*384 + c4]
    const float4* hid4 = reinterpret_cast<const float4*>(hidden);
    #pragma unroll
    for (int g = tid; g < BQ * C4; g += 256) {
        int gb  = g / C4;
        int gc4 = g - gb * C4;
        sh4[gc4 * SHSTRIDE + gb] = hid4[g];
    }
    __syncthreads();

    const int row = blockIdx.x * 16 + r;  // 0..4095
    const float4* wp = reinterpret_cast<const float4*>(wq + (size_t)row * CC);

    float acc = 0.0f;
    #pragma unroll 8
    for (int c4 = 0; c4 < C4; c4++) {
        float4 wv = wp[c4];               // broadcast across 16 lanes
        float4 hv = sh4[c4 * SHSTRIDE + b];
        acc += wv.x * hv.x + wv.y * hv.y + wv.z * hv.z + wv.w * hv.w;
    }
    // g_q layout [b][h][k] = b*4096 + row
    g_q[b * (NH * HD) + row] = acc + bq[row];
}

// ---------------------------------------------------------------------------
// Kernel 2: partial fused scores -> online softmax -> weighted V.
// grid = B*H*SPLIT = 2048 CTAs. blockIdx.x = bh*SPLIT + s.
// CTA handles l in [s*1024, (s+1)*1024); 8 warps, 128 l per warp.
// Writes unnormalized (M, den, num[128]) partials.
// ---------------------------------------------------------------------------
__global__ void __launch_bounds__(NW * 32) attn_partial_kernel(const float* __restrict__ Kd,
                                                               const float* __restrict__ Vd) {
    const int bhs  = blockIdx.x;
    const int s    = bhs & (SPLIT - 1);
    const int bh   = bhs >> 2;            // b*NH + h
    const int b    = bh >> 5;
    const int h    = bh & 31;
    const int warp = threadIdx.x >> 5;
    const int lane = threadIdx.x & 31;

    const float4 qv = *reinterpret_cast<const float4*>(g_q + (size_t)bh * HD + 4 * lane);

    const int S4   = NH * HD / 4;         // float4 stride between l's = 1024
    const int LPC  = LL / SPLIT;          // 1024 l per CTA
    const int LPW  = LPC / NW;            // 128 l per warp
    const int l0   = s * LPC + warp * LPW;
    const size_t base4 = (((size_t)b * LL) * NH + h) * (HD / 4);

    const float4* kp = reinterpret_cast<const float4*>(Kd) + base4 + (size_t)l0 * S4 + lane;
    const float4* vp = reinterpret_cast<const float4*>(Vd) + base4 + (size_t)l0 * S4 + lane;

    float m = -1e30f;
    float sden = 0.0f;
    float ax = 0.f, ay = 0.f, az = 0.f, aw = 0.f;

    #pragma unroll 1
    for (int i = 0; i < LPW; i += 4) {
        float4 kv[4], vv[4];
        #pragma unroll
        for (int u = 0; u < 4; u++) {
            kv[u] = kp[u * S4];
            vv[u] = vp[u * S4];
        }
        kp += 4 * S4;
        vp += 4 * S4;

        #pragma unroll
        for (int u = 0; u < 4; u++) {
            float x = kv[u].x * qv.x + kv[u].y * qv.y + kv[u].z * qv.z + kv[u].w * qv.w;
            x += __shfl_xor_sync(0xffffffffu, x, 16);
            x += __shfl_xor_sync(0xffffffffu, x, 8);
            x += __shfl_xor_sync(0xffffffffu, x, 4);
            x += __shfl_xor_sync(0xffffffffu, x, 2);
            x += __shfl_xor_sync(0xffffffffu, x, 1);

            if (x > m) {                  // warp-uniform, rare
                float sc = __expf(m - x);
                sden *= sc; ax *= sc; ay *= sc; az *= sc; aw *= sc;
                m = x;
            }
            float p = __expf(x - m);
            sden += p;
            ax += p * vv[u].x;
            ay += p * vv[u].y;
            az += p * vv[u].z;
            aw += p * vv[u].w;
        }
    }

    // Cross-warp merge within CTA.
    __shared__ float  sm_m[NW];
    __shared__ float  sm_s[NW];
    __shared__ float4 sm_acc[NW][32];

    if (lane == 0) { sm_m[warp] = m; sm_s[warp] = sden; }
    sm_acc[warp][lane] = make_float4(ax, ay, az, aw);
    __syncthreads();

    if (threadIdx.x < HD) {
        const int k = threadIdx.x;
        float M = sm_m[0];
        #pragma unroll
        for (int w = 1; w < NW; w++) M = fmaxf(M, sm_m[w]);
        float den = 0.0f, num = 0.0f;
        #pragma unroll
        for (int w = 0; w < NW; w++) {
            float e = __expf(sm_m[w] - M);
            den += e * sm_s[w];
            num += e * reinterpret_cast<const float*>(&sm_acc[w][0])[k];
        }
        g_pa[(size_t)bhs * HD + k] = num;
        if (k == 0) { g_pm[bhs] = M; g_ps[bhs] = den; }
    }
}

// ---------------------------------------------------------------------------
// Kernel 3: combine SPLIT partials per (b,h) and write output.
// grid = 512 blocks, 128 threads.
// ---------------------------------------------------------------------------
__global__ void __launch_bounds__(HD) combine_kernel(float* __restrict__ out) {
    const int bh = blockIdx.x;
    const int k  = threadIdx.x;

    float M = g_pm[bh * SPLIT];
    #pragma unroll
    for (int s = 1; s < SPLIT; s++) M = fmaxf(M, g_pm[bh * SPLIT + s]);

    float den = 0.0f, num = 0.0f;
    #pragma unroll
    for (int s = 0; s < SPLIT; s++) {
        float e = __expf(g_pm[bh * SPLIT + s] - M);
        den += e * g_ps[bh * SPLIT + s];
        num += e * g_pa[(size_t)(bh * SPLIT + s) * HD + k];
    }
    out[(size_t)bh * HD + k] = num / den;
}

// ---------------------------------------------------------------------------
// Inputs (metadata order): 0 hidden_states_q [B,1536] f32
//                          1 key_states      [B,L,H,HD] f32
//                          2 value_states    [B,L,H,HD] f32
//                          3 w_q             [H*HD,1536] f32
//                          4 b_q             [H*HD] f32
// Output: [B, H*HD] f32
// ---------------------------------------------------------------------------
extern "C" void kernel_launch(void* const* d_in, const int* in_sizes, int n_in,
                              void* d_out, int out_size) {
    (void)in_sizes; (void)n_in; (void)out_size;
    const float* hidden = (const float*)d_in[0];
    const float* Kd     = (const float*)d_in[1];
    const float* Vd     = (const float*)d_in[2];
    const float* wq     = (const float*)d_in[3];
    const float* bq     = (const float*)d_in[4];
    float* out          = (float*)d_out;

    const int qproj_smem = C4 * SHSTRIDE * sizeof(float4);   // ~104 KB
    static int attr_done = 0;
    if (!attr_done) {
        cudaFuncSetAttribute(qproj_kernel, cudaFuncAttributeMaxDynamicSharedMemorySize,
                             qproj_smem);
        attr_done = 1;
    }

    qproj_kernel<<<(NH * HD) / 16, 256, qproj_smem>>>(hidden, wq, bq);
    attn_partial_kernel<<<BQ * NH * SPLIT, NW * 32>>>(Kd, Vd);
    combine_kernel<<<BQ * NH, HD>>>(out);
}

// round 3
// speedup vs baseline: 1.2226x; 1.0820x over previous
#include <cuda_runtime.h>

#define BQ 16      // batch
#define NH 32      // heads
#define HD 128     // head dim
#define LL 4096    // seq len
#define CC 1536    // q_lora_rank
#define NW 8       // warps per attention CTA
#define SPLIT 4    // L-splits per (b,h)
#define C4 (CC / 4)   // 384 float4 per row

// Scratch for projected q: [B, H, HD] = 256 KB.
__device__ float g_q[BQ * NH * HD];
// Partial softmax results: indexed by bhs = (b*NH+h)*SPLIT + s.
__device__ float g_pm[BQ * NH * SPLIT];
__device__ float g_ps[BQ * NH * SPLIT];
__device__ float g_pa[BQ * NH * SPLIT * HD];

// ---------------------------------------------------------------------------
// Kernel 1: q = hidden @ w_q^T + b_q      (4096 x 1536 x 16 skinny GEMM)
// 256 blocks x 8 warps = 2048 warps. Warp g owns rows [4*(g>>1), +4) and
// batches [(g&1)*8, +8). Lane = contraction chunk (c4 = lane + 32*i) so all
// w_q loads are fully coalesced 512B LDG.128 transactions; w_q streamed from
// DRAM exactly once. acc[4][8] register block: 12 LDG.128 feed 128 FFMAs per
// step. Hidden (98 KB) is L1-resident after first touch. Cross-lane reduce
// via padded smem transpose.
// ---------------------------------------------------------------------------
__global__ void __launch_bounds__(256) qproj_kernel(const float* __restrict__ hidden,
                                                    const float* __restrict__ wq,
                                                    const float* __restrict__ bq) {
    const int tid  = threadIdx.x;
    const int warp = tid >> 5;
    const int lane = tid & 31;
    const int g    = blockIdx.x * 8 + warp;   // 0..2047
    const int row0 = (g >> 1) * 4;            // 4-row group
    const int b0   = (g & 1) * 8;             // batch half

    const float4* w4 = reinterpret_cast<const float4*>(wq);
    const float4* h4 = reinterpret_cast<const float4*>(hidden);

    float acc[4][8];
    #pragma unroll
    for (int r = 0; r < 4; r++)
        #pragma unroll
        for (int b = 0; b < 8; b++) acc[r][b] = 0.0f;

    #pragma unroll 2
    for (int i = 0; i < C4 / 32; i++) {       // 12 steps
        const int c4 = i * 32 + lane;
        float4 wv[4];
        #pragma unroll
        for (int r = 0; r < 4; r++)
            wv[r] = w4[(size_t)(row0 + r) * C4 + c4];
        #pragma unroll
        for (int b = 0; b < 8; b++) {
            float4 hv = h4[(b0 + b) * C4 + c4];
            #pragma unroll
            for (int r = 0; r < 4; r++) {
                acc[r][b] = fmaf(wv[r].x, hv.x,
                            fmaf(wv[r].y, hv.y,
                            fmaf(wv[r].z, hv.z,
                            fmaf(wv[r].w, hv.w, acc[r][b]))));
            }
        }
    }

    // Cross-lane reduction: transpose through padded smem (conflict-free).
    __shared__ float red[8][32][33];
    #pragma unroll
    for (int p = 0; p < 32; p++)
        red[warp][lane][p] = acc[p >> 3][p & 7];
    __syncwarp();

    // Lane p sums its (r, b) pair over all 32 contraction lanes.
    float s0 = 0.f, s1 = 0.f, s2 = 0.f, s3 = 0.f;
    #pragma unroll
    for (int j = 0; j < 32; j += 4) {
        s0 += red[warp][j + 0][lane];
        s1 += red[warp][j + 1][lane];
        s2 += red[warp][j + 2][lane];
        s3 += red[warp][j + 3][lane];
    }
    const int r   = lane >> 3;
    const int b   = b0 + (lane & 7);
    const int row = row0 + r;
    g_q[b * (NH * HD) + row] = (s0 + s1) + (s2 + s3) + bq[row];
}

// ---------------------------------------------------------------------------
// Kernel 2: partial fused scores -> online softmax -> weighted V.
// grid = B*H*SPLIT = 2048 CTAs. blockIdx.x = bh*SPLIT + s.
// CTA handles l in [s*1024, (s+1)*1024); 8 warps, 128 l per warp.
// Writes unnormalized (M, den, num[128]) partials.
// ---------------------------------------------------------------------------
__global__ void __launch_bounds__(NW * 32) attn_partial_kernel(const float* __restrict__ Kd,
                                                               const float* __restrict__ Vd) {
    const int bhs  = blockIdx.x;
    const int s    = bhs & (SPLIT - 1);
    const int bh   = bhs >> 2;            // b*NH + h
    const int b    = bh >> 5;
    const int h    = bh & 31;
    const int warp = threadIdx.x >> 5;
    const int lane = threadIdx.x & 31;

    const float4 qv = *reinterpret_cast<const float4*>(g_q + (size_t)bh * HD + 4 * lane);

    const int S4   = NH * HD / 4;         // float4 stride between l's = 1024
    const int LPC  = LL / SPLIT;          // 1024 l per CTA
    const int LPW  = LPC / NW;            // 128 l per warp
    const int l0   = s * LPC + warp * LPW;
    const size_t base4 = (((size_t)b * LL) * NH + h) * (HD / 4);

    const float4* kp = reinterpret_cast<const float4*>(Kd) + base4 + (size_t)l0 * S4 + lane;
    const float4* vp = reinterpret_cast<const float4*>(Vd) + base4 + (size_t)l0 * S4 + lane;

    float m = -1e30f;
    float sden = 0.0f;
    float ax = 0.f, ay = 0.f, az = 0.f, aw = 0.f;

    #pragma unroll 1
    for (int i = 0; i < LPW; i += 4) {
        float4 kv[4], vv[4];
        #pragma unroll
        for (int u = 0; u < 4; u++) {
            kv[u] = kp[u * S4];
            vv[u] = vp[u * S4];
        }
        kp += 4 * S4;
        vp += 4 * S4;

        #pragma unroll
        for (int u = 0; u < 4; u++) {
            float x = kv[u].x * qv.x + kv[u].y * qv.y + kv[u].z * qv.z + kv[u].w * qv.w;
            x += __shfl_xor_sync(0xffffffffu, x, 16);
            x += __shfl_xor_sync(0xffffffffu, x, 8);
            x += __shfl_xor_sync(0xffffffffu, x, 4);
            x += __shfl_xor_sync(0xffffffffu, x, 2);
            x += __shfl_xor_sync(0xffffffffu, x, 1);

            if (x > m) {                  // warp-uniform, rare
                float sc = __expf(m - x);
                sden *= sc; ax *= sc; ay *= sc; az *= sc; aw *= sc;
                m = x;
            }
            float p = __expf(x - m);
            sden += p;
            ax += p * vv[u].x;
            ay += p * vv[u].y;
            az += p * vv[u].z;
            aw += p * vv[u].w;
        }
    }

    // Cross-warp merge within CTA.
    __shared__ float  sm_m[NW];
    __shared__ float  sm_s[NW];
    __shared__ float4 sm_acc[NW][32];

    if (lane == 0) { sm_m[warp] = m; sm_s[warp] = sden; }
    sm_acc[warp][lane] = make_float4(ax, ay, az, aw);
    __syncthreads();

    if (threadIdx.x < HD) {
        const int k = threadIdx.x;
        float M = sm_m[0];
        #pragma unroll
        for (int w = 1; w < NW; w++) M = fmaxf(M, sm_m[w]);
        float den = 0.0f, num = 0.0f;
        #pragma unroll
        for (int w = 0; w < NW; w++) {
            float e = __expf(sm_m[w] - M);
            den += e * sm_s[w];
            num += e * reinterpret_cast<const float*>(&sm_acc[w][0])[k];
        }
        g_pa[(size_t)bhs * HD + k] = num;
        if (k == 0) { g_pm[bhs] = M; g_ps[bhs] = den; }
    }
}

// ---------------------------------------------------------------------------
// Kernel 3: combine SPLIT partials per (b,h) and write output.
// ---------------------------------------------------------------------------
__global__ void __launch_bounds__(HD) combine_kernel(float* __restrict__ out) {
    const int bh = blockIdx.x;
    const int k  = threadIdx.x;

    float M = g_pm[bh * SPLIT];
    #pragma unroll
    for (int s = 1; s < SPLIT; s++) M = fmaxf(M, g_pm[bh * SPLIT + s]);

    float den = 0.0f, num = 0.0f;
    #pragma unroll
    for (int s = 0; s < SPLIT; s++) {
        float e = __expf(g_pm[bh * SPLIT + s] - M);
        den += e * g_ps[bh * SPLIT + s];
        num += e * g_pa[(size_t)(bh * SPLIT + s) * HD + k];
    }
    out[(size_t)bh * HD + k] = num / den;
}

// ---------------------------------------------------------------------------
// Inputs (metadata order): 0 hidden_states_q [B,1536] f32
//                          1 key_states      [B,L,H,HD] f32
//                          2 value_states    [B,L,H,HD] f32
//                          3 w_q             [H*HD,1536] f32
//                          4 b_q             [H*HD] f32
// Output: [B, H*HD] f32
// ---------------------------------------------------------------------------
extern "C" void kernel_launch(void* const* d_in, const int* in_sizes, int n_in,
                              void* d_out, int out_size) {
    (void)in_sizes; (void)n_in; (void)out_size;
    const float* hidden = (const float*)d_in[0];
    const float* Kd     = (const float*)d_in[1];
    const float* Vd     = (const float*)d_in[2];
    const float* wq     = (const float*)d_in[3];
    const float* bq     = (const float*)d_in[4];
    float* out          = (float*)d_out;

    qproj_kernel<<<256, 256>>>(hidden, wq, bq);
    attn_partial_kernel<<<BQ * NH * SPLIT, NW * 32>>>(Kd, Vd);
    combine_kernel<<<BQ * NH, HD>>>(out);
}

// round 4
// speedup vs baseline: 1.2618x; 1.0320x over previous
#include <cuda_runtime.h>

#define BQ 16      // batch
#define NH 32      // heads
#define HD 128     // head dim
#define LL 4096    // seq len
#define CC 1536    // q_lora_rank
#define NW 8       // warps per attention CTA
#define SPLIT 4    // L-splits per (b,h)
#define C4 (CC / 4)   // 384 float4 per row
#define RPW 4      // qproj rows per warp

// Scratch for projected q: [B, H, HD] = 256 KB.
__device__ float g_q[BQ * NH * HD];
// Partial softmax results: indexed by bhs = (b*NH+h)*SPLIT + s.
__device__ float g_pm[BQ * NH * SPLIT];
__device__ float g_ps[BQ * NH * SPLIT];
__device__ float g_pa[BQ * NH * SPLIT * HD];
// Per-(b,h) arrival counters for fused combine (self-resetting, zero-init).
__device__ unsigned int g_cnt[BQ * NH];

// ---------------------------------------------------------------------------
// Kernel 1: q = hidden @ w_q^T + b_q      (4096 x 1536 x 16 skinny GEMM)
// 256 CTAs x 128 threads = 1024 warps; warp owns 4 rows x all 16 batches.
// Lane indexes the contraction (c4 = chunk*128 + st*32 + lane) so every w_q
// load is a coalesced 512B LDG.128, and w_q streams from DRAM exactly once.
// Per chunk, 16 independent w-loads are issued back-to-back BEFORE any
// dependent FMA (64 cache lines in flight per warp) to cover the 577-cyc
// DRAM latency. hidden (98 KB) is L1-resident after first touch.
// Cross-lane reduction via padded smem transpose (conflict-free).
// ---------------------------------------------------------------------------
__global__ void __launch_bounds__(128, 2) qproj_kernel(const float* __restrict__ hidden,
                                                       const float* __restrict__ wq,
                                                       const float* __restrict__ bq) {
    const int warp = threadIdx.x >> 5;
    const int lane = threadIdx.x & 31;
    const int gw   = blockIdx.x * 4 + warp;   // 0..1023
    const int row0 = gw * RPW;

    const float4* w4 = reinterpret_cast<const float4*>(wq);
    const float4* h4 = reinterpret_cast<const float4*>(hidden);

    float acc[RPW][BQ];
    #pragma unroll
    for (int r = 0; r < RPW; r++)
        #pragma unroll
        for (int b = 0; b < BQ; b++) acc[r][b] = 0.0f;

    #pragma unroll
    for (int chunk = 0; chunk < 3; chunk++) {     // 3 chunks x 4 steps = 384 c4
        // Front-batched w preload: 16 independent LDG.128.
        float4 wv[4][RPW];
        #pragma unroll
        for (int st = 0; st < 4; st++)
            #pragma unroll
            for (int r = 0; r < RPW; r++)
                wv[st][r] = w4[(size_t)(row0 + r) * C4 + chunk * 128 + st * 32 + lane];

        #pragma unroll
        for (int st = 0; st < 4; st++) {
            const int c4 = chunk * 128 + st * 32 + lane;
            #pragma unroll
            for (int b = 0; b < BQ; b++) {
                float4 hv = h4[b * C4 + c4];
                #pragma unroll
                for (int r = 0; r < RPW; r++) {
                    acc[r][b] = fmaf(wv[st][r].x, hv.x,
                                fmaf(wv[st][r].y, hv.y,
                                fmaf(wv[st][r].z, hv.z,
                                fmaf(wv[st][r].w, hv.w, acc[r][b]))));
                }
            }
        }
    }

    // Cross-lane reduction: 64 (r,b) outputs per warp via padded smem.
    __shared__ float red[4][32][65];
    #pragma unroll
    for (int r = 0; r < RPW; r++)
        #pragma unroll
        for (int b = 0; b < BQ; b++)
            red[warp][lane][r * BQ + b] = acc[r][b];
    __syncwarp();

    // Each lane produces outputs p = lane and p = lane + 32.
    #pragma unroll
    for (int half = 0; half < 2; half++) {
        const int p = lane + half * 32;
        float s0 = 0.f, s1 = 0.f, s2 = 0.f, s3 = 0.f;
        #pragma unroll
        for (int j = 0; j < 32; j += 4) {
            s0 += red[warp][j + 0][p];
            s1 += red[warp][j + 1][p];
            s2 += red[warp][j + 2][p];
            s3 += red[warp][j + 3][p];
        }
        const int r   = p >> 4;
        const int b   = p & 15;
        const int row = row0 + r;
        g_q[b * (NH * HD) + row] = (s0 + s1) + (s2 + s3) + bq[row];
    }
}

// ---------------------------------------------------------------------------
// Kernel 2: partial fused scores -> online softmax -> weighted V, with the
// final cross-split combine fused in (threadfence-reduction pattern: last
// arriving CTA of each (b,h)'s SPLIT group combines and resets the counter).
// grid = B*H*SPLIT = 2048 CTAs; 8 warps; warp streams 128 l's.
// ---------------------------------------------------------------------------
__global__ void __launch_bounds__(NW * 32) attn_kernel(const float* __restrict__ Kd,
                                                       const float* __restrict__ Vd,
                                                       float* __restrict__ out) {
    const int bhs  = blockIdx.x;
    const int s    = bhs & (SPLIT - 1);
    const int bh   = bhs >> 2;            // b*NH + h
    const int b    = bh >> 5;
    const int h    = bh & 31;
    const int warp = threadIdx.x >> 5;
    const int lane = threadIdx.x & 31;

    const float4 qv = *reinterpret_cast<const float4*>(g_q + (size_t)bh * HD + 4 * lane);

    const int S4   = NH * HD / 4;         // float4 stride between l's = 1024
    const int LPC  = LL / SPLIT;          // 1024 l per CTA
    const int LPW  = LPC / NW;            // 128 l per warp
    const int l0   = s * LPC + warp * LPW;
    const size_t base4 = (((size_t)b * LL) * NH + h) * (HD / 4);

    const float4* kp = reinterpret_cast<const float4*>(Kd) + base4 + (size_t)l0 * S4 + lane;
    const float4* vp = reinterpret_cast<const float4*>(Vd) + base4 + (size_t)l0 * S4 + lane;

    float m = -1e30f;
    float sden = 0.0f;
    float ax = 0.f, ay = 0.f, az = 0.f, aw = 0.f;

    #pragma unroll 1
    for (int i = 0; i < LPW; i += 4) {
        float4 kv[4], vv[4];
        #pragma unroll
        for (int u = 0; u < 4; u++) {
            kv[u] = __ldcs(kp + (size_t)u * S4);   // streaming, evict-first
            vv[u] = __ldcs(vp + (size_t)u * S4);
        }
        kp += 4 * S4;
        vp += 4 * S4;

        #pragma unroll
        for (int u = 0; u < 4; u++) {
            float x = kv[u].x * qv.x + kv[u].y * qv.y + kv[u].z * qv.z + kv[u].w * qv.w;
            x += __shfl_xor_sync(0xffffffffu, x, 16);
            x += __shfl_xor_sync(0xffffffffu, x, 8);
            x += __shfl_xor_sync(0xffffffffu, x, 4);
            x += __shfl_xor_sync(0xffffffffu, x, 2);
            x += __shfl_xor_sync(0xffffffffu, x, 1);

            if (x > m) {                  // warp-uniform, rare
                float sc = __expf(m - x);
                sden *= sc; ax *= sc; ay *= sc; az *= sc; aw *= sc;
                m = x;
            }
            float p = __expf(x - m);
            sden += p;
            ax += p * vv[u].x;
            ay += p * vv[u].y;
            az += p * vv[u].z;
            aw += p * vv[u].w;
        }
    }

    // Cross-warp merge within CTA.
    __shared__ float  sm_m[NW];
    __shared__ float  sm_s[NW];
    __shared__ float4 sm_acc[NW][32];

    if (lane == 0) { sm_m[warp] = m; sm_s[warp] = sden; }
    sm_acc[warp][lane] = make_float4(ax, ay, az, aw);
    __syncthreads();

    if (threadIdx.x < HD) {
        const int k = threadIdx.x;
        float M = sm_m[0];
        #pragma unroll
        for (int w = 1; w < NW; w++) M = fmaxf(M, sm_m[w]);
        float den = 0.0f, num = 0.0f;
        #pragma unroll
        for (int w = 0; w < NW; w++) {
            float e = __expf(sm_m[w] - M);
            den += e * sm_s[w];
            num += e * reinterpret_cast<const float*>(&sm_acc[w][0])[k];
        }
        g_pa[(size_t)bhs * HD + k] = num;
        if (k == 0) { g_pm[bhs] = M; g_ps[bhs] = den; }
    }

    // ---- Fused combine (threadfence reduction) ----
    __shared__ bool amLast;
    __threadfence();                      // make partials visible device-wide
    __syncthreads();
    if (threadIdx.x == 0) {
        unsigned int old = atomicAdd(&g_cnt[bh], 1u);
        amLast = (old == SPLIT - 1);
    }
    __syncthreads();

    if (amLast) {
        if (threadIdx.x < HD) {
            const int k = threadIdx.x;
            float M = g_pm[bh * SPLIT];
            #pragma unroll
            for (int t = 1; t < SPLIT; t++) M = fmaxf(M, g_pm[bh * SPLIT + t]);
            float den = 0.0f, num = 0.0f;
            #pragma unroll
            for (int t = 0; t < SPLIT; t++) {
                float e = __expf(g_pm[bh * SPLIT + t] - M);
                den += e * g_ps[bh * SPLIT + t];
                num += e * g_pa[(size_t)(bh * SPLIT + t) * HD + k];
            }
            out[(size_t)bh * HD + k] = num / den;
        }
        __syncthreads();
        if (threadIdx.x == 0) g_cnt[bh] = 0u;   // self-reset for next replay
    }
}

// ---------------------------------------------------------------------------
// Inputs (metadata order): 0 hidden_states_q [B,1536] f32
//                          1 key_states      [B,L,H,HD] f32
//                          2 value_states    [B,L,H,HD] f32
//                          3 w_q             [H*HD,1536] f32
//                          4 b_q             [H*HD] f32
// Output: [B, H*HD] f32
// ---------------------------------------------------------------------------
extern "C" void kernel_launch(void* const* d_in, const int* in_sizes, int n_in,
                              void* d_out, int out_size) {
    (void)in_sizes; (void)n_in; (void)out_size;
    const float* hidden = (const float*)d_in[0];
    const float* Kd     = (const float*)d_in[1];
    const float* Vd     = (const float*)d_in[2];
    const float* wq     = (const float*)d_in[3];
    const float* bq     = (const float*)d_in[4];
    float* out          = (float*)d_out;

    qproj_kernel<<<(NH * HD) / (RPW * 4), 128>>>(hidden, wq, bq);
    attn_kernel<<<BQ * NH * SPLIT, NW * 32>>>(Kd, Vd, out);
}